// round 1
// baseline (speedup 1.0000x reference)
#include <cuda_runtime.h>
#include <cstddef>

#define NMAX 100000
#define DHC  128

// Scratch (static __device__ arrays; no allocation allowed)
__device__ float g_dinv[NMAX];
__device__ float g_hs[(size_t)NMAX * DHC];
__device__ float g_t [(size_t)NMAX * DHC];
__device__ float g_h [(size_t)NMAX * DHC];

// ---------------------------------------------------------------------------
// Degree: deg[v] = #edges with dst==v  (float atomic; counts are exact < 2^24)
// ---------------------------------------------------------------------------
__global__ void deg_kernel(const int* __restrict__ ei, float* __restrict__ deg, int E) {
    int i = blockIdx.x * blockDim.x + threadIdx.x;
    int stride = gridDim.x * blockDim.x;
    for (; i < E; i += stride)
        atomicAdd(&deg[ei[E + i]], 1.0f);
}

__global__ void dinv_kernel(float* __restrict__ d, int n) {
    int i = blockIdx.x * blockDim.x + threadIdx.x;
    if (i < n) d[i] = rsqrtf(d[i] + 1.0f);
}

// ---------------------------------------------------------------------------
// SGEMM (M x K) @ (K x 128) with row-wise scale by dinv in the epilogue:
//   out[r, :] = (A[r, :] @ W) * dinv[r]
// BM=128, BN=128, BK=8, 256 threads, 8x8 microtile (N split 4+4 for
// conflict-free LDS.128).
// ---------------------------------------------------------------------------
__global__ __launch_bounds__(256) void gemm_scale_kernel(
    const float* __restrict__ A, const float* __restrict__ W,
    const float* __restrict__ dinv, float* __restrict__ out,
    int M, int K)
{
    constexpr int BM = 128, BN = 128, BK = 8;
    __shared__ float As[BK][BM];
    __shared__ float Ws[BK][BN];

    int tid = threadIdx.x;
    int tr = tid >> 4;        // 0..15 : row group
    int tc = tid & 15;        // 0..15 : col group
    int row0 = blockIdx.x * BM;

    int a_row = tid >> 1;          // 0..127
    int a_col = (tid & 1) * 4;     // 0 or 4
    int w_row = tid >> 5;          // 0..7
    int w_col = (tid & 31) * 4;    // 0..124

    float acc[8][8];
#pragma unroll
    for (int i = 0; i < 8; i++)
#pragma unroll
        for (int j = 0; j < 8; j++) acc[i][j] = 0.0f;

    for (int k0 = 0; k0 < K; k0 += BK) {
        float4 av = make_float4(0.f, 0.f, 0.f, 0.f);
        int gr = row0 + a_row;
        if (gr < M)
            av = *reinterpret_cast<const float4*>(A + (size_t)gr * K + k0 + a_col);
        As[a_col + 0][a_row] = av.x;
        As[a_col + 1][a_row] = av.y;
        As[a_col + 2][a_row] = av.z;
        As[a_col + 3][a_row] = av.w;

        float4 wv = *reinterpret_cast<const float4*>(W + (size_t)(k0 + w_row) * BN + w_col);
        *reinterpret_cast<float4*>(&Ws[w_row][w_col]) = wv;
        __syncthreads();

#pragma unroll
        for (int k = 0; k < BK; k++) {
            float4 ra0 = *reinterpret_cast<const float4*>(&As[k][tr * 8]);
            float4 ra1 = *reinterpret_cast<const float4*>(&As[k][tr * 8 + 4]);
            float4 rb0 = *reinterpret_cast<const float4*>(&Ws[k][tc * 4]);
            float4 rb1 = *reinterpret_cast<const float4*>(&Ws[k][64 + tc * 4]);
            float ra[8] = {ra0.x, ra0.y, ra0.z, ra0.w, ra1.x, ra1.y, ra1.z, ra1.w};
            float rb[8] = {rb0.x, rb0.y, rb0.z, rb0.w, rb1.x, rb1.y, rb1.z, rb1.w};
#pragma unroll
            for (int i = 0; i < 8; i++)
#pragma unroll
                for (int j = 0; j < 8; j++)
                    acc[i][j] = fmaf(ra[i], rb[j], acc[i][j]);
        }
        __syncthreads();
    }

#pragma unroll
    for (int i = 0; i < 8; i++) {
        int r = row0 + tr * 8 + i;
        if (r >= M) break;                 // rows ascend with i
        float s = dinv[r];
        float4 o0, o1;
        o0.x = acc[i][0] * s; o0.y = acc[i][1] * s;
        o0.z = acc[i][2] * s; o0.w = acc[i][3] * s;
        o1.x = acc[i][4] * s; o1.y = acc[i][5] * s;
        o1.z = acc[i][6] * s; o1.w = acc[i][7] * s;
        *reinterpret_cast<float4*>(out + (size_t)r * BN + tc * 4)      = o0;
        *reinterpret_cast<float4*>(out + (size_t)r * BN + 64 + tc * 4) = o1;
    }
}

// ---------------------------------------------------------------------------
// Edge scatter: t[dst, :] += hs[src, :]   (warp per edge; v4 fp32 reduction)
// ---------------------------------------------------------------------------
__global__ void scatter_kernel(const float* __restrict__ hs, const int* __restrict__ ei,
                               float* __restrict__ t, int E)
{
    int warp  = (blockIdx.x * blockDim.x + threadIdx.x) >> 5;
    int lane  = threadIdx.x & 31;
    int nwarp = (gridDim.x * blockDim.x) >> 5;
    for (int e = warp; e < E; e += nwarp) {
        int src = __ldg(&ei[e]);
        int dst = __ldg(&ei[E + e]);
        float4 v = *reinterpret_cast<const float4*>(hs + (size_t)src * DHC + lane * 4);
        float* q = t + (size_t)dst * DHC + lane * 4;
        asm volatile("red.global.add.v4.f32 [%0], {%1,%2,%3,%4};"
                     :: "l"(q), "f"(v.x), "f"(v.y), "f"(v.z), "f"(v.w) : "memory");
    }
}

// ---------------------------------------------------------------------------
// Finalize: out[v,c] = [relu]( dinv[v]*(t[v,c] + hs[v,c]) + b[c] )
// ---------------------------------------------------------------------------
__global__ void finalize_kernel(const float* __restrict__ t, const float* __restrict__ hs,
                                const float* __restrict__ dinv, const float* __restrict__ b,
                                float* __restrict__ out, int n, int relu)
{
    int total = n * (DHC / 4);
    int idx = blockIdx.x * blockDim.x + threadIdx.x;
    int stride = gridDim.x * blockDim.x;
    for (; idx < total; idx += stride) {
        int row = idx >> 5;       // DHC/4 = 32 float4 per row
        int c4  = idx & 31;
        float s = __ldg(&dinv[row]);
        float4 tv = *reinterpret_cast<const float4*>(t  + ((size_t)idx << 2));
        float4 hv = *reinterpret_cast<const float4*>(hs + ((size_t)idx << 2));
        float4 bv = *reinterpret_cast<const float4*>(b + c4 * 4);
        float4 r;
        r.x = fmaf(s, tv.x + hv.x, bv.x);
        r.y = fmaf(s, tv.y + hv.y, bv.y);
        r.z = fmaf(s, tv.z + hv.z, bv.z);
        r.w = fmaf(s, tv.w + hv.w, bv.w);
        if (relu) {
            r.x = fmaxf(r.x, 0.f); r.y = fmaxf(r.y, 0.f);
            r.z = fmaxf(r.z, 0.f); r.w = fmaxf(r.w, 0.f);
        }
        *reinterpret_cast<float4*>(out + ((size_t)idx << 2)) = r;
    }
}

// ---------------------------------------------------------------------------
// Decode: out[e] = dot(z[i,:], z[j,:])   (warp per pair)
// ---------------------------------------------------------------------------
__global__ void decode_kernel(const float* __restrict__ z, const int* __restrict__ eli,
                              float* __restrict__ out, int EL)
{
    int warp  = (blockIdx.x * blockDim.x + threadIdx.x) >> 5;
    int lane  = threadIdx.x & 31;
    int nwarp = (gridDim.x * blockDim.x) >> 5;
    for (int e = warp; e < EL; e += nwarp) {
        int i = __ldg(&eli[e]);
        int j = __ldg(&eli[EL + e]);
        float4 a = *reinterpret_cast<const float4*>(z + (size_t)i * DHC + lane * 4);
        float4 b = *reinterpret_cast<const float4*>(z + (size_t)j * DHC + lane * 4);
        float d = a.x * b.x + a.y * b.y + a.z * b.z + a.w * b.w;
#pragma unroll
        for (int off = 16; off; off >>= 1)
            d += __shfl_xor_sync(0xffffffff, d, off);
        if (lane == 0) out[e] = d;
    }
}

// ---------------------------------------------------------------------------
extern "C" void kernel_launch(void* const* d_in, const int* in_sizes, int n_in,
                              void* d_out, int out_size)
{
    const float* x  = (const float*)d_in[0];
    const int*   ei = (const int*)  d_in[1];
    const int*   eli= (const int*)  d_in[2];
    const float* W1 = (const float*)d_in[3];
    const float* b1 = (const float*)d_in[4];
    const float* W2 = (const float*)d_in[5];
    const float* b2 = (const float*)d_in[6];
    float* out = (float*)d_out;

    const int DIN = 256;
    int N  = in_sizes[0] / DIN;
    int E  = in_sizes[1] / 2;
    int EL = in_sizes[2] / 2;

    float *p_dinv, *p_hs, *p_t, *p_h;
    cudaGetSymbolAddress((void**)&p_dinv, g_dinv);
    cudaGetSymbolAddress((void**)&p_hs,   g_hs);
    cudaGetSymbolAddress((void**)&p_t,    g_t);
    cudaGetSymbolAddress((void**)&p_h,    g_h);

    // degrees -> dinv
    cudaMemsetAsync(p_dinv, 0, (size_t)N * sizeof(float));
    deg_kernel<<<1024, 256>>>(ei, p_dinv, E);
    dinv_kernel<<<(N + 255) / 256, 256>>>(p_dinv, N);

    int gemm_blocks = (N + 127) / 128;

    // ---- layer 1 ----
    gemm_scale_kernel<<<gemm_blocks, 256>>>(x, W1, p_dinv, p_hs, N, DIN);
    cudaMemsetAsync(p_t, 0, (size_t)N * DHC * sizeof(float));
    scatter_kernel<<<2048, 256>>>(p_hs, ei, p_t, E);
    finalize_kernel<<<4096, 256>>>(p_t, p_hs, p_dinv, b1, p_h, N, 1);

    // ---- layer 2 ----
    gemm_scale_kernel<<<gemm_blocks, 256>>>(p_h, W2, p_dinv, p_hs, N, DHC);
    cudaMemsetAsync(p_t, 0, (size_t)N * DHC * sizeof(float));
    scatter_kernel<<<2048, 256>>>(p_hs, ei, p_t, E);
    finalize_kernel<<<4096, 256>>>(p_t, p_hs, p_dinv, b2, p_h, N, 0);

    // ---- decode ----
    decode_kernel<<<(EL * 32 + 255) / 256, 256>>>(p_h, eli, out, EL);
}

// round 3
// speedup vs baseline: 1.3658x; 1.3658x over previous
#include <cuda_runtime.h>
#include <cstddef>

#define NMAX 100000
#define EMAX 1600000
#define DHC  128

// Scratch (static __device__ arrays; no allocation allowed)
__device__ float g_dinv[NMAX];
__device__ int   g_degi[NMAX];
__device__ int   g_offs[NMAX];
__device__ int   g_cursor[NMAX];
__device__ int   g_csr[EMAX];
__device__ int   g_bsum[1024];
__device__ float g_hs[(size_t)NMAX * DHC];
__device__ float g_h [(size_t)NMAX * DHC];
__device__ float g_z [(size_t)NMAX * DHC];

// ---------------------------------------------------------------------------
// Degree histogram (int)
// ---------------------------------------------------------------------------
__global__ void deg_kernel(const int* __restrict__ ei, int* __restrict__ deg, int E) {
    int i = blockIdx.x * blockDim.x + threadIdx.x;
    int stride = gridDim.x * blockDim.x;
    for (; i < E; i += stride)
        atomicAdd(&deg[ei[E + i]], 1);
}

__global__ void dinv_kernel(const int* __restrict__ deg, float* __restrict__ d, int n) {
    int i = blockIdx.x * blockDim.x + threadIdx.x;
    if (i < n) d[i] = rsqrtf((float)deg[i] + 1.0f);
}

// ---------------------------------------------------------------------------
// 3-phase exclusive prefix scan of deg -> offs
// ---------------------------------------------------------------------------
__global__ void scan_phase1(const int* __restrict__ deg, int* __restrict__ offs,
                            int* __restrict__ bsum, int n) {
    __shared__ int sh[1024];
    int i = blockIdx.x * 1024 + threadIdx.x;
    int v = (i < n) ? deg[i] : 0;
    sh[threadIdx.x] = v;
    __syncthreads();
    for (int d = 1; d < 1024; d <<= 1) {
        int t = (threadIdx.x >= d) ? sh[threadIdx.x - d] : 0;
        __syncthreads();
        sh[threadIdx.x] += t;
        __syncthreads();
    }
    if (i < n) offs[i] = sh[threadIdx.x] - v;   // exclusive
    if (threadIdx.x == 1023) bsum[blockIdx.x] = sh[1023];
}

__global__ void scan_phase2(int* __restrict__ bsum, int nb) {
    __shared__ int sh[1024];
    int v = (threadIdx.x < nb) ? bsum[threadIdx.x] : 0;
    sh[threadIdx.x] = v;
    __syncthreads();
    for (int d = 1; d < 1024; d <<= 1) {
        int t = (threadIdx.x >= d) ? sh[threadIdx.x - d] : 0;
        __syncthreads();
        sh[threadIdx.x] += t;
        __syncthreads();
    }
    if (threadIdx.x < nb) bsum[threadIdx.x] = sh[threadIdx.x] - v;  // exclusive
}

__global__ void scan_phase3(int* __restrict__ offs, const int* __restrict__ bsum, int n) {
    int i = blockIdx.x * 1024 + threadIdx.x;
    if (i < n) offs[i] += bsum[blockIdx.x];
}

// ---------------------------------------------------------------------------
// CSR fill: bucket src by dst
// ---------------------------------------------------------------------------
__global__ void fill_kernel(const int* __restrict__ ei, const int* __restrict__ offs,
                            int* __restrict__ cursor, int* __restrict__ csr, int E) {
    int i = blockIdx.x * blockDim.x + threadIdx.x;
    int stride = gridDim.x * blockDim.x;
    for (; i < E; i += stride) {
        int src = ei[i];
        int dst = ei[E + i];
        int pos = offs[dst] + atomicAdd(&cursor[dst], 1);
        csr[pos] = src;
    }
}

// ---------------------------------------------------------------------------
// SGEMM (M x K) @ (K x 128), epilogue scales row r by dinv[r]:
//   out[r, :] = (A[r, :] @ W) * dinv[r]
// ---------------------------------------------------------------------------
__global__ __launch_bounds__(256) void gemm_scale_kernel(
    const float* __restrict__ A, const float* __restrict__ W,
    const float* __restrict__ dinv, float* __restrict__ out,
    int M, int K)
{
    constexpr int BM = 128, BN = 128, BK = 8;
    __shared__ float As[BK][BM];
    __shared__ float Ws[BK][BN];

    int tid = threadIdx.x;
    int tr = tid >> 4;
    int tc = tid & 15;
    int row0 = blockIdx.x * BM;

    int a_row = tid >> 1;
    int a_col = (tid & 1) * 4;
    int w_row = tid >> 5;
    int w_col = (tid & 31) * 4;

    float acc[8][8];
#pragma unroll
    for (int i = 0; i < 8; i++)
#pragma unroll
        for (int j = 0; j < 8; j++) acc[i][j] = 0.0f;

    for (int k0 = 0; k0 < K; k0 += BK) {
        float4 av = make_float4(0.f, 0.f, 0.f, 0.f);
        int gr = row0 + a_row;
        if (gr < M)
            av = *reinterpret_cast<const float4*>(A + (size_t)gr * K + k0 + a_col);
        As[a_col + 0][a_row] = av.x;
        As[a_col + 1][a_row] = av.y;
        As[a_col + 2][a_row] = av.z;
        As[a_col + 3][a_row] = av.w;

        float4 wv = *reinterpret_cast<const float4*>(W + (size_t)(k0 + w_row) * BN + w_col);
        *reinterpret_cast<float4*>(&Ws[w_row][w_col]) = wv;
        __syncthreads();

#pragma unroll
        for (int k = 0; k < BK; k++) {
            float4 ra0 = *reinterpret_cast<const float4*>(&As[k][tr * 8]);
            float4 ra1 = *reinterpret_cast<const float4*>(&As[k][tr * 8 + 4]);
            float4 rb0 = *reinterpret_cast<const float4*>(&Ws[k][tc * 4]);
            float4 rb1 = *reinterpret_cast<const float4*>(&Ws[k][64 + tc * 4]);
            float ra[8] = {ra0.x, ra0.y, ra0.z, ra0.w, ra1.x, ra1.y, ra1.z, ra1.w};
            float rb[8] = {rb0.x, rb0.y, rb0.z, rb0.w, rb1.x, rb1.y, rb1.z, rb1.w};
#pragma unroll
            for (int i = 0; i < 8; i++)
#pragma unroll
                for (int j = 0; j < 8; j++)
                    acc[i][j] = fmaf(ra[i], rb[j], acc[i][j]);
        }
        __syncthreads();
    }

#pragma unroll
    for (int i = 0; i < 8; i++) {
        int r = row0 + tr * 8 + i;
        if (r >= M) break;
        float s = dinv[r];
        float4 o0, o1;
        o0.x = acc[i][0] * s; o0.y = acc[i][1] * s;
        o0.z = acc[i][2] * s; o0.w = acc[i][3] * s;
        o1.x = acc[i][4] * s; o1.y = acc[i][5] * s;
        o1.z = acc[i][6] * s; o1.w = acc[i][7] * s;
        *reinterpret_cast<float4*>(out + (size_t)r * BN + tc * 4)      = o0;
        *reinterpret_cast<float4*>(out + (size_t)r * BN + 64 + tc * 4) = o1;
    }
}

// ---------------------------------------------------------------------------
// Fused gather + self-loop + scale + bias (+relu):
//   out[v,:] = act( dinv[v] * ( sum_{e in in(v)} hs[src_e,:] + hs[v,:] ) + b )
// Warp per node; lane covers 4 contiguous floats.
// ---------------------------------------------------------------------------
__global__ void gather_fused_kernel(
    const float* __restrict__ hs, const int* __restrict__ csr,
    const int* __restrict__ offs, const int* __restrict__ deg,
    const float* __restrict__ dinv, const float* __restrict__ b,
    float* __restrict__ out, int n, int relu)
{
    int warp = (blockIdx.x * blockDim.x + threadIdx.x) >> 5;
    int lane = threadIdx.x & 31;
    if (warp >= n) return;

    int start = offs[warp];
    int d     = deg[warp];

    // self term
    float4 acc = *reinterpret_cast<const float4*>(hs + (size_t)warp * DHC + lane * 4);

    for (int base = 0; base < d; base += 32) {
        int idx = base + lane;
        int s = (idx < d) ? csr[start + idx] : 0;
        int m = min(32, d - base);
        for (int j = 0; j < m; j++) {
            int sj = __shfl_sync(0xffffffffu, s, j);
            float4 v = *reinterpret_cast<const float4*>(hs + (size_t)sj * DHC + lane * 4);
            acc.x += v.x; acc.y += v.y; acc.z += v.z; acc.w += v.w;
        }
    }

    float sc = dinv[warp];
    float4 bv = *reinterpret_cast<const float4*>(b + lane * 4);
    float4 r;
    r.x = fmaf(sc, acc.x, bv.x);
    r.y = fmaf(sc, acc.y, bv.y);
    r.z = fmaf(sc, acc.z, bv.z);
    r.w = fmaf(sc, acc.w, bv.w);
    if (relu) {
        r.x = fmaxf(r.x, 0.f); r.y = fmaxf(r.y, 0.f);
        r.z = fmaxf(r.z, 0.f); r.w = fmaxf(r.w, 0.f);
    }
    *reinterpret_cast<float4*>(out + (size_t)warp * DHC + lane * 4) = r;
}

// ---------------------------------------------------------------------------
// Decode: out[e] = dot(z[i,:], z[j,:])   (warp per pair)
// ---------------------------------------------------------------------------
__global__ void decode_kernel(const float* __restrict__ z, const int* __restrict__ eli,
                              float* __restrict__ out, int EL)
{
    int warp  = (blockIdx.x * blockDim.x + threadIdx.x) >> 5;
    int lane  = threadIdx.x & 31;
    int nwarp = (gridDim.x * blockDim.x) >> 5;
    for (int e = warp; e < EL; e += nwarp) {
        int i = __ldg(&eli[e]);
        int j = __ldg(&eli[EL + e]);
        float4 a = *reinterpret_cast<const float4*>(z + (size_t)i * DHC + lane * 4);
        float4 b = *reinterpret_cast<const float4*>(z + (size_t)j * DHC + lane * 4);
        float d = a.x * b.x + a.y * b.y + a.z * b.z + a.w * b.w;
#pragma unroll
        for (int off = 16; off; off >>= 1)
            d += __shfl_xor_sync(0xffffffff, d, off);
        if (lane == 0) out[e] = d;
    }
}

// ---------------------------------------------------------------------------
extern "C" void kernel_launch(void* const* d_in, const int* in_sizes, int n_in,
                              void* d_out, int out_size)
{
    const float* x  = (const float*)d_in[0];
    const int*   ei = (const int*)  d_in[1];
    const int*   eli= (const int*)  d_in[2];
    const float* W1 = (const float*)d_in[3];
    const float* b1 = (const float*)d_in[4];
    const float* W2 = (const float*)d_in[5];
    const float* b2 = (const float*)d_in[6];
    float* out = (float*)d_out;

    const int DIN = 256;
    int N  = in_sizes[0] / DIN;
    int E  = in_sizes[1] / 2;
    int EL = in_sizes[2] / 2;

    float *p_dinv, *p_hs, *p_h, *p_z;
    int *p_degi, *p_offs, *p_cursor, *p_csr, *p_bsum;
    cudaGetSymbolAddress((void**)&p_dinv,   g_dinv);
    cudaGetSymbolAddress((void**)&p_degi,   g_degi);
    cudaGetSymbolAddress((void**)&p_offs,   g_offs);
    cudaGetSymbolAddress((void**)&p_cursor, g_cursor);
    cudaGetSymbolAddress((void**)&p_csr,    g_csr);
    cudaGetSymbolAddress((void**)&p_bsum,   g_bsum);
    cudaGetSymbolAddress((void**)&p_hs,     g_hs);
    cudaGetSymbolAddress((void**)&p_h,      g_h);
    cudaGetSymbolAddress((void**)&p_z,      g_z);

    // ---- CSR build (once, reused for both layers) ----
    cudaMemsetAsync(p_degi,   0, (size_t)N * sizeof(int));
    cudaMemsetAsync(p_cursor, 0, (size_t)N * sizeof(int));
    deg_kernel<<<1024, 256>>>(ei, p_degi, E);
    dinv_kernel<<<(N + 255) / 256, 256>>>(p_degi, p_dinv, N);

    int nb = (N + 1023) / 1024;
    scan_phase1<<<nb, 1024>>>(p_degi, p_offs, p_bsum, N);
    scan_phase2<<<1, 1024>>>(p_bsum, nb);
    scan_phase3<<<nb, 1024>>>(p_offs, p_bsum, N);
    fill_kernel<<<1024, 256>>>(ei, p_offs, p_cursor, p_csr, E);

    int gemm_blocks = (N + 127) / 128;
    int gather_blocks = (N * 32 + 255) / 256;

    // ---- layer 1 ----
    gemm_scale_kernel<<<gemm_blocks, 256>>>(x, W1, p_dinv, p_hs, N, DIN);
    gather_fused_kernel<<<gather_blocks, 256>>>(p_hs, p_csr, p_offs, p_degi,
                                                p_dinv, b1, p_h, N, 1);

    // ---- layer 2 ----
    gemm_scale_kernel<<<gemm_blocks, 256>>>(p_h, W2, p_dinv, p_hs, N, DHC);
    gather_fused_kernel<<<gather_blocks, 256>>>(p_hs, p_csr, p_offs, p_degi,
                                                p_dinv, b2, p_z, N, 0);

    // ---- decode ----
    decode_kernel<<<(EL * 32 + 255) / 256, 256>>>(p_z, eli, out, EL);
}

// round 4
// speedup vs baseline: 2.0140x; 1.4746x over previous
#include <cuda_runtime.h>
#include <cstddef>
#include <cstdint>

#define NMAX 100000
#define EMAX 1600000
#define DHC  128

// Scratch (static __device__ arrays; no allocation allowed)
__device__ float g_dinv[NMAX];
__device__ int   g_degi[NMAX];
__device__ int   g_offs[NMAX];
__device__ int   g_cursor[NMAX];
__device__ int   g_csr[EMAX];
__device__ int   g_bsum[1024];
__device__ float g_hs[(size_t)NMAX * DHC];
__device__ float g_h [(size_t)NMAX * DHC];
__device__ float g_z [(size_t)NMAX * DHC];

// ---------------------------------------------------------------------------
// Degree histogram (int)
// ---------------------------------------------------------------------------
__global__ void deg_kernel(const int* __restrict__ ei, int* __restrict__ deg, int E) {
    int i = blockIdx.x * blockDim.x + threadIdx.x;
    int stride = gridDim.x * blockDim.x;
    for (; i < E; i += stride)
        atomicAdd(&deg[ei[E + i]], 1);
}

__global__ void dinv_kernel(const int* __restrict__ deg, float* __restrict__ d, int n) {
    int i = blockIdx.x * blockDim.x + threadIdx.x;
    if (i < n) d[i] = rsqrtf((float)deg[i] + 1.0f);
}

// ---------------------------------------------------------------------------
// 3-phase exclusive prefix scan of deg -> offs
// ---------------------------------------------------------------------------
__global__ void scan_phase1(const int* __restrict__ deg, int* __restrict__ offs,
                            int* __restrict__ bsum, int n) {
    __shared__ int sh[1024];
    int i = blockIdx.x * 1024 + threadIdx.x;
    int v = (i < n) ? deg[i] : 0;
    sh[threadIdx.x] = v;
    __syncthreads();
    for (int d = 1; d < 1024; d <<= 1) {
        int t = (threadIdx.x >= d) ? sh[threadIdx.x - d] : 0;
        __syncthreads();
        sh[threadIdx.x] += t;
        __syncthreads();
    }
    if (i < n) offs[i] = sh[threadIdx.x] - v;   // exclusive
    if (threadIdx.x == 1023) bsum[blockIdx.x] = sh[1023];
}

__global__ void scan_phase2(int* __restrict__ bsum, int nb) {
    __shared__ int sh[1024];
    int v = (threadIdx.x < nb) ? bsum[threadIdx.x] : 0;
    sh[threadIdx.x] = v;
    __syncthreads();
    for (int d = 1; d < 1024; d <<= 1) {
        int t = (threadIdx.x >= d) ? sh[threadIdx.x - d] : 0;
        __syncthreads();
        sh[threadIdx.x] += t;
        __syncthreads();
    }
    if (threadIdx.x < nb) bsum[threadIdx.x] = sh[threadIdx.x] - v;  // exclusive
}

__global__ void scan_phase3(int* __restrict__ offs, const int* __restrict__ bsum, int n) {
    int i = blockIdx.x * 1024 + threadIdx.x;
    if (i < n) offs[i] += bsum[blockIdx.x];
}

// ---------------------------------------------------------------------------
// CSR fill: bucket src by dst
// ---------------------------------------------------------------------------
__global__ void fill_kernel(const int* __restrict__ ei, const int* __restrict__ offs,
                            int* __restrict__ cursor, int* __restrict__ csr, int E) {
    int i = blockIdx.x * blockDim.x + threadIdx.x;
    int stride = gridDim.x * blockDim.x;
    for (; i < E; i += stride) {
        int src = ei[i];
        int dst = ei[E + i];
        int pos = offs[dst] + atomicAdd(&cursor[dst], 1);
        csr[pos] = src;
    }
}

// ---------------------------------------------------------------------------
// TF32 tensor-core GEMM: out[r,:] = (A[r,:K] @ W[K,128]) * dinv[r]
// BM=128 BN=128 BK=16, 256 threads = 8 warps (4x2), warp tile 32x64.
// mma.sync.m16n8k8 tf32. Conflict-free SMEM: As[128][20], Bs[16][136].
// ---------------------------------------------------------------------------
__device__ __forceinline__ uint32_t f2tf32(float x) {
    uint32_t r;
    asm("cvt.rna.tf32.f32 %0, %1;" : "=r"(r) : "f"(x));
    return r;
}

__global__ __launch_bounds__(256, 2) void gemm_tf32_kernel(
    const float* __restrict__ A, const float* __restrict__ W,
    const float* __restrict__ dinv, float* __restrict__ out,
    int M, int K)
{
    constexpr int BM = 128, BN = 128, BK = 16;
    constexpr int ASTR = BK + 4;   // 20 floats
    constexpr int BSTR = BN + 8;   // 136 floats
    __shared__ uint32_t As[BM * ASTR];
    __shared__ uint32_t Bs[BK * BSTR];

    const int tid  = threadIdx.x;
    const int wid  = tid >> 5;
    const int lane = tid & 31;
    const int g    = lane >> 2;    // 0..7
    const int t    = lane & 3;     // 0..3
    const int warpM = wid >> 1;    // 0..3 -> 32-row tile
    const int warpN = wid & 1;     // 0..1 -> 64-col tile
    const int row0 = blockIdx.x * BM;

    // A loads: 512 float4 per tile, 2 per thread
    const int aIdx0 = tid, aIdx1 = tid + 256;
    const int ar0 = aIdx0 >> 2, ac0 = (aIdx0 & 3) * 4;
    const int ar1 = aIdx1 >> 2, ac1 = (aIdx1 & 3) * 4;
    // B loads: 16 rows x 32 float4, 2 rows per warp-pair
    const int br0 = wid, br1 = wid + 8;
    const int bc  = lane * 4;

    float acc[2][8][4];
#pragma unroll
    for (int mi = 0; mi < 2; mi++)
#pragma unroll
        for (int ni = 0; ni < 8; ni++)
#pragma unroll
            for (int c = 0; c < 4; c++) acc[mi][ni][c] = 0.0f;

    float4 aPre0, aPre1, bPre0, bPre1;
    {
        int r = row0 + ar0;
        aPre0 = (r < M) ? *reinterpret_cast<const float4*>(A + (size_t)r * K + ac0)
                        : make_float4(0.f, 0.f, 0.f, 0.f);
        r = row0 + ar1;
        aPre1 = (r < M) ? *reinterpret_cast<const float4*>(A + (size_t)r * K + ac1)
                        : make_float4(0.f, 0.f, 0.f, 0.f);
        bPre0 = *reinterpret_cast<const float4*>(W + (size_t)br0 * BN + bc);
        bPre1 = *reinterpret_cast<const float4*>(W + (size_t)br1 * BN + bc);
    }

    const int mBase = warpM * 32;
    const int nBase = warpN * 64;

    for (int k0 = 0; k0 < K; k0 += BK) {
        // store prefetched tile (tf32-converted)
        {
            uint32_t* p = &As[ar0 * ASTR + ac0];
            p[0] = f2tf32(aPre0.x); p[1] = f2tf32(aPre0.y);
            p[2] = f2tf32(aPre0.z); p[3] = f2tf32(aPre0.w);
            p = &As[ar1 * ASTR + ac1];
            p[0] = f2tf32(aPre1.x); p[1] = f2tf32(aPre1.y);
            p[2] = f2tf32(aPre1.z); p[3] = f2tf32(aPre1.w);
            p = &Bs[br0 * BSTR + bc];
            p[0] = f2tf32(bPre0.x); p[1] = f2tf32(bPre0.y);
            p[2] = f2tf32(bPre0.z); p[3] = f2tf32(bPre0.w);
            p = &Bs[br1 * BSTR + bc];
            p[0] = f2tf32(bPre1.x); p[1] = f2tf32(bPre1.y);
            p[2] = f2tf32(bPre1.z); p[3] = f2tf32(bPre1.w);
        }
        __syncthreads();

        if (k0 + BK < K) {
            int kn = k0 + BK;
            int r = row0 + ar0;
            aPre0 = (r < M) ? *reinterpret_cast<const float4*>(A + (size_t)r * K + kn + ac0)
                            : make_float4(0.f, 0.f, 0.f, 0.f);
            r = row0 + ar1;
            aPre1 = (r < M) ? *reinterpret_cast<const float4*>(A + (size_t)r * K + kn + ac1)
                            : make_float4(0.f, 0.f, 0.f, 0.f);
            bPre0 = *reinterpret_cast<const float4*>(W + (size_t)(kn + br0) * BN + bc);
            bPre1 = *reinterpret_cast<const float4*>(W + (size_t)(kn + br1) * BN + bc);
        }

#pragma unroll
        for (int ks = 0; ks < 2; ks++) {
            const int kb = ks * 8;
            uint32_t af[2][4];
#pragma unroll
            for (int mi = 0; mi < 2; mi++) {
                int m = mBase + mi * 16 + g;
                af[mi][0] = As[(m    ) * ASTR + kb + t];
                af[mi][1] = As[(m + 8) * ASTR + kb + t];
                af[mi][2] = As[(m    ) * ASTR + kb + t + 4];
                af[mi][3] = As[(m + 8) * ASTR + kb + t + 4];
            }
            uint32_t bf[8][2];
#pragma unroll
            for (int ni = 0; ni < 8; ni++) {
                int n = nBase + ni * 8 + g;
                bf[ni][0] = Bs[(kb + t    ) * BSTR + n];
                bf[ni][1] = Bs[(kb + t + 4) * BSTR + n];
            }
#pragma unroll
            for (int mi = 0; mi < 2; mi++)
#pragma unroll
                for (int ni = 0; ni < 8; ni++) {
                    asm volatile(
                        "mma.sync.aligned.m16n8k8.row.col.f32.tf32.tf32.f32 "
                        "{%0,%1,%2,%3}, {%4,%5,%6,%7}, {%8,%9}, {%0,%1,%2,%3};"
                        : "+f"(acc[mi][ni][0]), "+f"(acc[mi][ni][1]),
                          "+f"(acc[mi][ni][2]), "+f"(acc[mi][ni][3])
                        : "r"(af[mi][0]), "r"(af[mi][1]), "r"(af[mi][2]), "r"(af[mi][3]),
                          "r"(bf[ni][0]), "r"(bf[ni][1]));
                }
        }
        __syncthreads();
    }

    // epilogue: scale by dinv, store
#pragma unroll
    for (int mi = 0; mi < 2; mi++) {
        int m0 = row0 + mBase + mi * 16 + g;
        int m1 = m0 + 8;
        float s0 = (m0 < M) ? __ldg(&dinv[m0]) : 0.f;
        float s1 = (m1 < M) ? __ldg(&dinv[m1]) : 0.f;
#pragma unroll
        for (int ni = 0; ni < 8; ni++) {
            int col = nBase + ni * 8 + 2 * t;
            if (m0 < M) {
                float2 v = make_float2(acc[mi][ni][0] * s0, acc[mi][ni][1] * s0);
                *reinterpret_cast<float2*>(out + (size_t)m0 * BN + col) = v;
            }
            if (m1 < M) {
                float2 v = make_float2(acc[mi][ni][2] * s1, acc[mi][ni][3] * s1);
                *reinterpret_cast<float2*>(out + (size_t)m1 * BN + col) = v;
            }
        }
    }
}

// ---------------------------------------------------------------------------
// Fused gather + self-loop + scale + bias (+relu):
//   out[v,:] = act( dinv[v] * ( sum_{e in in(v)} hs[src_e,:] + hs[v,:] ) + b )
// ---------------------------------------------------------------------------
__global__ void gather_fused_kernel(
    const float* __restrict__ hs, const int* __restrict__ csr,
    const int* __restrict__ offs, const int* __restrict__ deg,
    const float* __restrict__ dinv, const float* __restrict__ b,
    float* __restrict__ out, int n, int relu)
{
    int warp = (blockIdx.x * blockDim.x + threadIdx.x) >> 5;
    int lane = threadIdx.x & 31;
    if (warp >= n) return;

    int start = offs[warp];
    int d     = deg[warp];

    float4 acc = *reinterpret_cast<const float4*>(hs + (size_t)warp * DHC + lane * 4);

    for (int base = 0; base < d; base += 32) {
        int idx = base + lane;
        int s = (idx < d) ? csr[start + idx] : 0;
        int m = min(32, d - base);
        for (int j = 0; j < m; j++) {
            int sj = __shfl_sync(0xffffffffu, s, j);
            float4 v = *reinterpret_cast<const float4*>(hs + (size_t)sj * DHC + lane * 4);
            acc.x += v.x; acc.y += v.y; acc.z += v.z; acc.w += v.w;
        }
    }

    float sc = dinv[warp];
    float4 bv = *reinterpret_cast<const float4*>(b + lane * 4);
    float4 r;
    r.x = fmaf(sc, acc.x, bv.x);
    r.y = fmaf(sc, acc.y, bv.y);
    r.z = fmaf(sc, acc.z, bv.z);
    r.w = fmaf(sc, acc.w, bv.w);
    if (relu) {
        r.x = fmaxf(r.x, 0.f); r.y = fmaxf(r.y, 0.f);
        r.z = fmaxf(r.z, 0.f); r.w = fmaxf(r.w, 0.f);
    }
    *reinterpret_cast<float4*>(out + (size_t)warp * DHC + lane * 4) = r;
}

// ---------------------------------------------------------------------------
// Decode: out[e] = dot(z[i,:], z[j,:])   (warp per pair)
// ---------------------------------------------------------------------------
__global__ void decode_kernel(const float* __restrict__ z, const int* __restrict__ eli,
                              float* __restrict__ out, int EL)
{
    int warp  = (blockIdx.x * blockDim.x + threadIdx.x) >> 5;
    int lane  = threadIdx.x & 31;
    int nwarp = (gridDim.x * blockDim.x) >> 5;
    for (int e = warp; e < EL; e += nwarp) {
        int i = __ldg(&eli[e]);
        int j = __ldg(&eli[EL + e]);
        float4 a = *reinterpret_cast<const float4*>(z + (size_t)i * DHC + lane * 4);
        float4 b = *reinterpret_cast<const float4*>(z + (size_t)j * DHC + lane * 4);
        float d = a.x * b.x + a.y * b.y + a.z * b.z + a.w * b.w;
#pragma unroll
        for (int off = 16; off; off >>= 1)
            d += __shfl_xor_sync(0xffffffff, d, off);
        if (lane == 0) out[e] = d;
    }
}

// ---------------------------------------------------------------------------
extern "C" void kernel_launch(void* const* d_in, const int* in_sizes, int n_in,
                              void* d_out, int out_size)
{
    const float* x  = (const float*)d_in[0];
    const int*   ei = (const int*)  d_in[1];
    const int*   eli= (const int*)  d_in[2];
    const float* W1 = (const float*)d_in[3];
    const float* b1 = (const float*)d_in[4];
    const float* W2 = (const float*)d_in[5];
    const float* b2 = (const float*)d_in[6];
    float* out = (float*)d_out;

    const int DIN = 256;
    int N  = in_sizes[0] / DIN;
    int E  = in_sizes[1] / 2;
    int EL = in_sizes[2] / 2;

    float *p_dinv, *p_hs, *p_h, *p_z;
    int *p_degi, *p_offs, *p_cursor, *p_csr, *p_bsum;
    cudaGetSymbolAddress((void**)&p_dinv,   g_dinv);
    cudaGetSymbolAddress((void**)&p_degi,   g_degi);
    cudaGetSymbolAddress((void**)&p_offs,   g_offs);
    cudaGetSymbolAddress((void**)&p_cursor, g_cursor);
    cudaGetSymbolAddress((void**)&p_csr,    g_csr);
    cudaGetSymbolAddress((void**)&p_bsum,   g_bsum);
    cudaGetSymbolAddress((void**)&p_hs,     g_hs);
    cudaGetSymbolAddress((void**)&p_h,      g_h);
    cudaGetSymbolAddress((void**)&p_z,      g_z);

    // ---- CSR build (once, reused for both layers) ----
    cudaMemsetAsync(p_degi,   0, (size_t)N * sizeof(int));
    cudaMemsetAsync(p_cursor, 0, (size_t)N * sizeof(int));
    deg_kernel<<<1024, 256>>>(ei, p_degi, E);
    dinv_kernel<<<(N + 255) / 256, 256>>>(p_degi, p_dinv, N);

    int nb = (N + 1023) / 1024;
    scan_phase1<<<nb, 1024>>>(p_degi, p_offs, p_bsum, N);
    scan_phase2<<<1, 1024>>>(p_bsum, nb);
    scan_phase3<<<nb, 1024>>>(p_offs, p_bsum, N);
    fill_kernel<<<1024, 256>>>(ei, p_offs, p_cursor, p_csr, E);

    int gemm_blocks = (N + 127) / 128;
    int gather_blocks = (N * 32 + 255) / 256;

    // ---- layer 1 ----
    gemm_tf32_kernel<<<gemm_blocks, 256>>>(x, W1, p_dinv, p_hs, N, DIN);
    gather_fused_kernel<<<gather_blocks, 256>>>(p_hs, p_csr, p_offs, p_degi,
                                                p_dinv, b1, p_h, N, 1);

    // ---- layer 2 ----
    gemm_tf32_kernel<<<gemm_blocks, 256>>>(p_h, W2, p_dinv, p_hs, N, DHC);
    gather_fused_kernel<<<gather_blocks, 256>>>(p_hs, p_csr, p_offs, p_degi,
                                                p_dinv, b2, p_z, N, 0);

    // ---- decode ----
    decode_kernel<<<(EL * 32 + 255) / 256, 256>>>(p_z, eli, out, EL);
}

// round 12
// speedup vs baseline: 2.5081x; 1.2453x over previous
#include <cuda_runtime.h>
#include <cuda_fp16.h>
#include <cstddef>
#include <cstdint>

#define NMAX 100000
#define EMAX 1600000
#define DHC  128

// Scratch (static __device__ arrays; no allocation allowed)
__device__ float  g_dinv[NMAX];
__device__ int    g_degi[NMAX];
__device__ int    g_offs[NMAX];
__device__ int    g_cursor[NMAX];
__device__ int    g_csr[EMAX];
__device__ int    g_bsum[1024];
__device__ __half g_hs[(size_t)NMAX * DHC];
__device__ __half g_h [(size_t)NMAX * DHC];
__device__ __half g_z [(size_t)NMAX * DHC];

// ---------------------------------------------------------------------------
// Degree histogram (int)
// ---------------------------------------------------------------------------
__global__ void deg_kernel(const int* __restrict__ ei, int* __restrict__ deg, int E) {
    int i = blockIdx.x * blockDim.x + threadIdx.x;
    int stride = gridDim.x * blockDim.x;
    for (; i < E; i += stride)
        atomicAdd(&deg[ei[E + i]], 1);
}

__global__ void dinv_kernel(const int* __restrict__ deg, float* __restrict__ d, int n) {
    int i = blockIdx.x * blockDim.x + threadIdx.x;
    if (i < n) d[i] = rsqrtf((float)deg[i] + 1.0f);
}

// ---------------------------------------------------------------------------
// 3-phase exclusive prefix scan of deg -> offs
// ---------------------------------------------------------------------------
__global__ void scan_phase1(const int* __restrict__ deg, int* __restrict__ offs,
                            int* __restrict__ bsum, int n) {
    __shared__ int sh[1024];
    int i = blockIdx.x * 1024 + threadIdx.x;
    int v = (i < n) ? deg[i] : 0;
    sh[threadIdx.x] = v;
    __syncthreads();
    for (int d = 1; d < 1024; d <<= 1) {
        int t = (threadIdx.x >= d) ? sh[threadIdx.x - d] : 0;
        __syncthreads();
        sh[threadIdx.x] += t;
        __syncthreads();
    }
    if (i < n) offs[i] = sh[threadIdx.x] - v;   // exclusive
    if (threadIdx.x == 1023) bsum[blockIdx.x] = sh[1023];
}

__global__ void scan_phase2(int* __restrict__ bsum, int nb) {
    __shared__ int sh[1024];
    int v = (threadIdx.x < nb) ? bsum[threadIdx.x] : 0;
    sh[threadIdx.x] = v;
    __syncthreads();
    for (int d = 1; d < 1024; d <<= 1) {
        int t = (threadIdx.x >= d) ? sh[threadIdx.x - d] : 0;
        __syncthreads();
        sh[threadIdx.x] += t;
        __syncthreads();
    }
    if (threadIdx.x < nb) bsum[threadIdx.x] = sh[threadIdx.x] - v;  // exclusive
}

__global__ void scan_phase3(int* __restrict__ offs, const int* __restrict__ bsum, int n) {
    int i = blockIdx.x * 1024 + threadIdx.x;
    if (i < n) offs[i] += bsum[blockIdx.x];
}

// ---------------------------------------------------------------------------
// CSR fill: bucket src by dst
// ---------------------------------------------------------------------------
__global__ void fill_kernel(const int* __restrict__ ei, const int* __restrict__ offs,
                            int* __restrict__ cursor, int* __restrict__ csr, int E) {
    int i = blockIdx.x * blockDim.x + threadIdx.x;
    int stride = gridDim.x * blockDim.x;
    for (; i < E; i += stride) {
        int src = ei[i];
        int dst = ei[E + i];
        int pos = offs[dst] + atomicAdd(&cursor[dst], 1);
        csr[pos] = src;
    }
}

// ---------------------------------------------------------------------------
// TF32 tensor-core GEMM: out_fp16[r,:] = (A[r,:K] @ W[K,128]) * dinv[r]
// A is fp32 (AHALF=false) or fp16 (AHALF=true; fp16 is exact in tf32).
// BM=128 BN=128 BK=16, 256 threads = 8 warps (4x2), warp tile 32x64.
// SMEM: As[128][20], Bs[16][136] (conflict-free strides).
// ---------------------------------------------------------------------------
__device__ __forceinline__ uint32_t f2tf32(float x) {
    uint32_t r;
    asm("cvt.rna.tf32.f32 %0, %1;" : "=r"(r) : "f"(x));
    return r;
}

template<bool AHALF>
__global__ __launch_bounds__(256, 2) void gemm_tf32_kernel(
    const void* __restrict__ Av, const float* __restrict__ W,
    const float* __restrict__ dinv, __half* __restrict__ out,
    int M, int K)
{
    constexpr int BM = 128, BN = 128, BK = 16;
    constexpr int ASTR = BK + 4;   // 20
    constexpr int BSTR = BN + 8;   // 136
    __shared__ uint32_t As[BM * ASTR];
    __shared__ uint32_t Bs[BK * BSTR];

    const int tid  = threadIdx.x;
    const int wid  = tid >> 5;
    const int lane = tid & 31;
    const int g    = lane >> 2;
    const int t    = lane & 3;
    const int warpM = wid >> 1;
    const int warpN = wid & 1;
    const int row0 = blockIdx.x * BM;

    // fp32-A load map: 512 float4/tile (128 rows x 4 float4), 2 per thread
    const int ar0 = tid >> 2;            // 0..63
    const int ac0 = (tid & 3) * 4;       // 0,4,8,12
    const int ar1 = ar0 + 64;            // 64..127
    // fp16-A load map: 256 uint4/tile (128 rows x 2 uint4 of 8 halves), 1 per thread
    const int arh = tid >> 1, ach = (tid & 1) * 8;
    // B load map: 16 rows x 32 float4; 2 rows per thread-group
    const int br0 = wid, br1 = wid + 8;
    const int bc  = lane * 4;

    float acc[2][8][4];
#pragma unroll
    for (int mi = 0; mi < 2; mi++)
#pragma unroll
        for (int ni = 0; ni < 8; ni++)
#pragma unroll
            for (int c = 0; c < 4; c++) acc[mi][ni][c] = 0.0f;

    float4 aPre0, aPre1, bPre0, bPre1;
    uint4  aPreH;
    {
        if (AHALF) {
            const __half* A = (const __half*)Av;
            int r = row0 + arh;
            aPreH = (r < M) ? *reinterpret_cast<const uint4*>(A + (size_t)r * K + ach)
                            : make_uint4(0, 0, 0, 0);
        } else {
            const float* A = (const float*)Av;
            int r = row0 + ar0;
            aPre0 = (r < M) ? *reinterpret_cast<const float4*>(A + (size_t)r * K + ac0)
                            : make_float4(0.f, 0.f, 0.f, 0.f);
            r = row0 + ar1;
            aPre1 = (r < M) ? *reinterpret_cast<const float4*>(A + (size_t)r * K + ac0)
                            : make_float4(0.f, 0.f, 0.f, 0.f);
        }
        bPre0 = *reinterpret_cast<const float4*>(W + (size_t)br0 * BN + bc);
        bPre1 = *reinterpret_cast<const float4*>(W + (size_t)br1 * BN + bc);
    }

    const int mBase = warpM * 32;
    const int nBase = warpN * 64;

    for (int k0 = 0; k0 < K; k0 += BK) {
        if (AHALF) {
            uint32_t* p = &As[arh * ASTR + ach];
            const __half2* hp = reinterpret_cast<const __half2*>(&aPreH);
#pragma unroll
            for (int q = 0; q < 4; q++) {
                float2 f = __half22float2(hp[q]);
                p[2 * q    ] = f2tf32(f.x);
                p[2 * q + 1] = f2tf32(f.y);
            }
        } else {
            uint32_t* p = &As[ar0 * ASTR + ac0];
            p[0] = f2tf32(aPre0.x); p[1] = f2tf32(aPre0.y);
            p[2] = f2tf32(aPre0.z); p[3] = f2tf32(aPre0.w);
            p = &As[ar1 * ASTR + ac0];
            p[0] = f2tf32(aPre1.x); p[1] = f2tf32(aPre1.y);
            p[2] = f2tf32(aPre1.z); p[3] = f2tf32(aPre1.w);
        }
        {
            uint32_t* p = &Bs[br0 * BSTR + bc];
            p[0] = f2tf32(bPre0.x); p[1] = f2tf32(bPre0.y);
            p[2] = f2tf32(bPre0.z); p[3] = f2tf32(bPre0.w);
            p = &Bs[br1 * BSTR + bc];
            p[0] = f2tf32(bPre1.x); p[1] = f2tf32(bPre1.y);
            p[2] = f2tf32(bPre1.z); p[3] = f2tf32(bPre1.w);
        }
        __syncthreads();

        if (k0 + BK < K) {
            int kn = k0 + BK;
            if (AHALF) {
                const __half* A = (const __half*)Av;
                int r = row0 + arh;
                aPreH = (r < M) ? *reinterpret_cast<const uint4*>(A + (size_t)r * K + kn + ach)
                                : make_uint4(0, 0, 0, 0);
            } else {
                const float* A = (const float*)Av;
                int r = row0 + ar0;
                aPre0 = (r < M) ? *reinterpret_cast<const float4*>(A + (size_t)r * K + kn + ac0)
                                : make_float4(0.f, 0.f, 0.f, 0.f);
                r = row0 + ar1;
                aPre1 = (r < M) ? *reinterpret_cast<const float4*>(A + (size_t)r * K + kn + ac0)
                                : make_float4(0.f, 0.f, 0.f, 0.f);
            }
            bPre0 = *reinterpret_cast<const float4*>(W + (size_t)(kn + br0) * BN + bc);
            bPre1 = *reinterpret_cast<const float4*>(W + (size_t)(kn + br1) * BN + bc);
        }

#pragma unroll
        for (int ks = 0; ks < 2; ks++) {
            const int kb = ks * 8;
            uint32_t af[2][4];
#pragma unroll
            for (int mi = 0; mi < 2; mi++) {
                int m = mBase + mi * 16 + g;
                af[mi][0] = As[(m    ) * ASTR + kb + t];
                af[mi][1] = As[(m + 8) * ASTR + kb + t];
                af[mi][2] = As[(m    ) * ASTR + kb + t + 4];
                af[mi][3] = As[(m + 8) * ASTR + kb + t + 4];
            }
            uint32_t bf[8][2];
#pragma unroll
            for (int ni = 0; ni < 8; ni++) {
                int n = nBase + ni * 8 + g;
                bf[ni][0] = Bs[(kb + t    ) * BSTR + n];
                bf[ni][1] = Bs[(kb + t + 4) * BSTR + n];
            }
#pragma unroll
            for (int mi = 0; mi < 2; mi++)
#pragma unroll
                for (int ni = 0; ni < 8; ni++) {
                    asm volatile(
                        "mma.sync.aligned.m16n8k8.row.col.f32.tf32.tf32.f32 "
                        "{%0,%1,%2,%3}, {%4,%5,%6,%7}, {%8,%9}, {%0,%1,%2,%3};"
                        : "+f"(acc[mi][ni][0]), "+f"(acc[mi][ni][1]),
                          "+f"(acc[mi][ni][2]), "+f"(acc[mi][ni][3])
                        : "r"(af[mi][0]), "r"(af[mi][1]), "r"(af[mi][2]), "r"(af[mi][3]),
                          "r"(bf[ni][0]), "r"(bf[ni][1]));
                }
        }
        __syncthreads();
    }

    // epilogue: scale by dinv, convert to fp16, store half2
#pragma unroll
    for (int mi = 0; mi < 2; mi++) {
        int m0 = row0 + mBase + mi * 16 + g;
        int m1 = m0 + 8;
        float s0 = (m0 < M) ? __ldg(&dinv[m0]) : 0.f;
        float s1 = (m1 < M) ? __ldg(&dinv[m1]) : 0.f;
#pragma unroll
        for (int ni = 0; ni < 8; ni++) {
            int col = nBase + ni * 8 + 2 * t;
            if (m0 < M) {
                __half2 v = __floats2half2_rn(acc[mi][ni][0] * s0, acc[mi][ni][1] * s0);
                *reinterpret_cast<__half2*>(out + (size_t)m0 * BN + col) = v;
            }
            if (m1 < M) {
                __half2 v = __floats2half2_rn(acc[mi][ni][2] * s1, acc[mi][ni][3] * s1);
                *reinterpret_cast<__half2*>(out + (size_t)m1 * BN + col) = v;
            }
        }
    }
}

// ---------------------------------------------------------------------------
// Fused gather (fp16 in/out, fp32 accumulate):
//   out[v,:] = act( dinv[v] * ( sum_{e in in(v)} hs[src_e,:] + hs[v,:] ) + b )
// Warp per node; lane covers 4 halves (8 B).
// ---------------------------------------------------------------------------
__global__ void gather_fused_kernel(
    const __half* __restrict__ hs, const int* __restrict__ csr,
    const int* __restrict__ offs, const int* __restrict__ deg,
    const float* __restrict__ dinv, const float* __restrict__ b,
    __half* __restrict__ out, int n, int relu)
{
    int warp = (blockIdx.x * blockDim.x + threadIdx.x) >> 5;
    int lane = threadIdx.x & 31;
    if (warp >= n) return;

    int start = offs[warp];
    int d     = deg[warp];
    const int c = lane * 4;

    float4 acc;
    {
        uint2 raw = *reinterpret_cast<const uint2*>(hs + (size_t)warp * DHC + c);
        float2 f01 = __half22float2(*reinterpret_cast<__half2*>(&raw.x));
        float2 f23 = __half22float2(*reinterpret_cast<__half2*>(&raw.y));
        acc = make_float4(f01.x, f01.y, f23.x, f23.y);
    }

    for (int base = 0; base < d; base += 32) {
        int idx = base + lane;
        int s = (idx < d) ? csr[start + idx] : 0;
        int m = min(32, d - base);
        for (int j = 0; j < m; j++) {
            int sj = __shfl_sync(0xffffffffu, s, j);
            uint2 raw = *reinterpret_cast<const uint2*>(hs + (size_t)sj * DHC + c);
            float2 f01 = __half22float2(*reinterpret_cast<__half2*>(&raw.x));
            float2 f23 = __half22float2(*reinterpret_cast<__half2*>(&raw.y));
            acc.x += f01.x; acc.y += f01.y; acc.z += f23.x; acc.w += f23.y;
        }
    }

    float sc = dinv[warp];
    float4 bv = *reinterpret_cast<const float4*>(b + c);
    float4 r;
    r.x = fmaf(sc, acc.x, bv.x);
    r.y = fmaf(sc, acc.y, bv.y);
    r.z = fmaf(sc, acc.z, bv.z);
    r.w = fmaf(sc, acc.w, bv.w);
    if (relu) {
        r.x = fmaxf(r.x, 0.f); r.y = fmaxf(r.y, 0.f);
        r.z = fmaxf(r.z, 0.f); r.w = fmaxf(r.w, 0.f);
    }
    uint2 o;
    *reinterpret_cast<__half2*>(&o.x) = __floats2half2_rn(r.x, r.y);
    *reinterpret_cast<__half2*>(&o.y) = __floats2half2_rn(r.z, r.w);
    *reinterpret_cast<uint2*>(out + (size_t)warp * DHC + c) = o;
}

// ---------------------------------------------------------------------------
// Decode: out[e] = dot(z[i,:], z[j,:])   (warp per pair, fp16 rows)
// ---------------------------------------------------------------------------
__global__ void decode_kernel(const __half* __restrict__ z, const int* __restrict__ eli,
                              float* __restrict__ out, int EL)
{
    int warp  = (blockIdx.x * blockDim.x + threadIdx.x) >> 5;
    int lane  = threadIdx.x & 31;
    int nwarp = (gridDim.x * blockDim.x) >> 5;
    const int c = lane * 4;
    for (int e = warp; e < EL; e += nwarp) {
        int i = __ldg(&eli[e]);
        int j = __ldg(&eli[EL + e]);
        uint2 ra = *reinterpret_cast<const uint2*>(z + (size_t)i * DHC + c);
        uint2 rb = *reinterpret_cast<const uint2*>(z + (size_t)j * DHC + c);
        float2 a01 = __half22float2(*reinterpret_cast<__half2*>(&ra.x));
        float2 a23 = __half22float2(*reinterpret_cast<__half2*>(&ra.y));
        float2 b01 = __half22float2(*reinterpret_cast<__half2*>(&rb.x));
        float2 b23 = __half22float2(*reinterpret_cast<__half2*>(&rb.y));
        float d = a01.x * b01.x + a01.y * b01.y + a23.x * b23.x + a23.y * b23.y;
#pragma unroll
        for (int off = 16; off; off >>= 1)
            d += __shfl_xor_sync(0xffffffff, d, off);
        if (lane == 0) out[e] = d;
    }
}

// ---------------------------------------------------------------------------
extern "C" void kernel_launch(void* const* d_in, const int* in_sizes, int n_in,
                              void* d_out, int out_size)
{
    const float* x  = (const float*)d_in[0];
    const int*   ei = (const int*)  d_in[1];
    const int*   eli= (const int*)  d_in[2];
    const float* W1 = (const float*)d_in[3];
    const float* b1 = (const float*)d_in[4];
    const float* W2 = (const float*)d_in[5];
    const float* b2 = (const float*)d_in[6];
    float* out = (float*)d_out;

    const int DIN = 256;
    int N  = in_sizes[0] / DIN;
    int E  = in_sizes[1] / 2;
    int EL = in_sizes[2] / 2;

    float *p_dinv;
    __half *p_hs, *p_h, *p_z;
    int *p_degi, *p_offs, *p_cursor, *p_csr, *p_bsum;
    cudaGetSymbolAddress((void**)&p_dinv,   g_dinv);
    cudaGetSymbolAddress((void**)&p_degi,   g_degi);
    cudaGetSymbolAddress((void**)&p_offs,   g_offs);
    cudaGetSymbolAddress((void**)&p_cursor, g_cursor);
    cudaGetSymbolAddress((void**)&p_csr,    g_csr);
    cudaGetSymbolAddress((void**)&p_bsum,   g_bsum);
    cudaGetSymbolAddress((void**)&p_hs,     g_hs);
    cudaGetSymbolAddress((void**)&p_h,      g_h);
    cudaGetSymbolAddress((void**)&p_z,      g_z);

    // ---- CSR build (once, reused for both layers) ----
    cudaMemsetAsync(p_degi,   0, (size_t)N * sizeof(int));
    cudaMemsetAsync(p_cursor, 0, (size_t)N * sizeof(int));
    deg_kernel<<<2048, 256>>>(ei, p_degi, E);
    dinv_kernel<<<(N + 255) / 256, 256>>>(p_degi, p_dinv, N);

    int nb = (N + 1023) / 1024;
    scan_phase1<<<nb, 1024>>>(p_degi, p_offs, p_bsum, N);
    scan_phase2<<<1, 1024>>>(p_bsum, nb);
    scan_phase3<<<nb, 1024>>>(p_offs, p_bsum, N);
    fill_kernel<<<2048, 256>>>(ei, p_offs, p_cursor, p_csr, E);

    int gemm_blocks = (N + 127) / 128;
    int gather_blocks = (N * 32 + 255) / 256;

    // ---- layer 1 ----
    gemm_tf32_kernel<false><<<gemm_blocks, 256>>>(x, W1, p_dinv, p_hs, N, DIN);
    gather_fused_kernel<<<gather_blocks, 256>>>(p_hs, p_csr, p_offs, p_degi,
                                                p_dinv, b1, p_h, N, 1);

    // ---- layer 2 ----
    gemm_tf32_kernel<true><<<gemm_blocks, 256>>>(p_h, W2, p_dinv, p_hs, N, DHC);
    gather_fused_kernel<<<gather_blocks, 256>>>(p_hs, p_csr, p_offs, p_degi,
                                                p_dinv, b2, p_z, N, 0);

    // ---- decode ----
    decode_kernel<<<(EL * 32 + 255) / 256, 256>>>(p_z, eli, out, EL);
}